// round 4
// baseline (speedup 1.0000x reference)
#include <cuda_runtime.h>
#include <cuda_bf16.h>
#include <math.h>

// Problem constants (fixed by the reference setup)
#define BB   8
#define TT   1024
#define TEE  1024
#define HH   1024
#define NHH  8
#define DKK  128
#define MM   (BB * TT)       // 8192 rows for projections
#define FF   4096            // FFN hidden

// ---------------------------------------------------------------------------
// Scratch (static device globals; allocation inside kernel_launch is banned)
// Flash attention removes the 256 MB scores buffer entirely.
// ---------------------------------------------------------------------------
__device__ float ws_xn [MM * HH];          // layernorm output (reused)
__device__ float ws_q  [MM * HH];
__device__ float ws_k  [MM * HH];
__device__ float ws_v  [MM * HH];
__device__ float ws_x  [MM * HH];          // x = input + self_attn
__device__ float ws_z  [MM * HH];          // z = x + cross_attn
__device__ float ws_ctx[MM * HH];          // attention context
__device__ float ws_h  [MM * FF];          // FFN hidden (128 MB)

// ---------------------------------------------------------------------------
// Flexible tiled GEMM:  C[m,n] = alpha * sum_k A[m,k] * B'[k,n]  (+ epilogue)
//   BT=true : B stored [N,K] row-major (ldb)   -> B'[k,n] = B[n*ldb + k]
// Tile: 128x128x8, 256 threads, 8x8 per thread, double-buffered smem.
// Requires: M,N divisible by 128; K divisible by 8.
// ---------------------------------------------------------------------------
template<bool BT>
__global__ __launch_bounds__(256)
void gemm_tile_kernel(const float* __restrict__ A, int lda,
                      const float* __restrict__ B, int ldb,
                      float*       __restrict__ C, int ldc,
                      int M, int N, int K, float alpha,
                      const float* __restrict__ bias,
                      const float* __restrict__ resid, int ldres,
                      int relu)
{
    __shared__ float As[2][8][128];
    __shared__ float Bs[2][8][128];

    const int m0 = blockIdx.y * 128;
    const int n0 = blockIdx.x * 128;
    const int tid = threadIdx.x;
    const int tx = tid & 15;
    const int ty = tid >> 4;

    float acc[8][8];
    #pragma unroll
    for (int i = 0; i < 8; ++i)
        #pragma unroll
        for (int j = 0; j < 8; ++j) acc[i][j] = 0.f;

    const int arow = tid >> 1;
    const int acol = (tid & 1) * 4;
    int brow, bcol;
    if (BT) { brow = tid >> 1; bcol = (tid & 1) * 4; }
    else    { brow = tid >> 5; bcol = (tid & 31) * 4; }

    const float* Aptr = A + (long long)(m0 + arow) * lda + acol;
    const float* Bptr;
    if (BT) Bptr = B + (long long)(n0 + brow) * ldb + bcol;
    else    Bptr = B + (long long)brow * ldb + n0 + bcol;

    const int nt = K >> 3;

    float4 avr = *(const float4*)(Aptr);
    float4 bvr = *(const float4*)(Bptr);
    As[0][acol + 0][arow] = avr.x;
    As[0][acol + 1][arow] = avr.y;
    As[0][acol + 2][arow] = avr.z;
    As[0][acol + 3][arow] = avr.w;
    if (BT) {
        Bs[0][bcol + 0][brow] = bvr.x;
        Bs[0][bcol + 1][brow] = bvr.y;
        Bs[0][bcol + 2][brow] = bvr.z;
        Bs[0][bcol + 3][brow] = bvr.w;
    } else {
        *(float4*)&Bs[0][brow][bcol] = bvr;
    }
    __syncthreads();

    for (int t = 0; t < nt; ++t) {
        const int cur = t & 1;
        if (t + 1 < nt) {
            const long long ko = (long long)(t + 1) * 8;
            avr = *(const float4*)(Aptr + ko);
            if (BT) bvr = *(const float4*)(Bptr + ko);
            else    bvr = *(const float4*)(Bptr + ko * ldb);
        }

        #pragma unroll
        for (int kk = 0; kk < 8; ++kk) {
            float a[8], bf[8];
            *(float4*)&a[0]  = *(const float4*)&As[cur][kk][ty * 4];
            *(float4*)&a[4]  = *(const float4*)&As[cur][kk][64 + ty * 4];
            *(float4*)&bf[0] = *(const float4*)&Bs[cur][kk][tx * 4];
            *(float4*)&bf[4] = *(const float4*)&Bs[cur][kk][64 + tx * 4];
            #pragma unroll
            for (int i = 0; i < 8; ++i)
                #pragma unroll
                for (int j = 0; j < 8; ++j)
                    acc[i][j] += a[i] * bf[j];
        }

        if (t + 1 < nt) {
            const int nxt = cur ^ 1;
            As[nxt][acol + 0][arow] = avr.x;
            As[nxt][acol + 1][arow] = avr.y;
            As[nxt][acol + 2][arow] = avr.z;
            As[nxt][acol + 3][arow] = avr.w;
            if (BT) {
                Bs[nxt][bcol + 0][brow] = bvr.x;
                Bs[nxt][bcol + 1][brow] = bvr.y;
                Bs[nxt][bcol + 2][brow] = bvr.z;
                Bs[nxt][bcol + 3][brow] = bvr.w;
            } else {
                *(float4*)&Bs[nxt][brow][bcol] = bvr;
            }
            __syncthreads();
        }
    }

    #pragma unroll
    for (int i = 0; i < 8; ++i) {
        const int mm = m0 + ((i < 4) ? (ty * 4 + i) : (64 + ty * 4 + i - 4));
        #pragma unroll
        for (int jh = 0; jh < 2; ++jh) {
            const int nn = n0 + jh * 64 + tx * 4;
            float4 r;
            r.x = acc[i][jh * 4 + 0] * alpha;
            r.y = acc[i][jh * 4 + 1] * alpha;
            r.z = acc[i][jh * 4 + 2] * alpha;
            r.w = acc[i][jh * 4 + 3] * alpha;
            if (bias) {
                float4 b4 = *(const float4*)(bias + nn);
                r.x += b4.x; r.y += b4.y; r.z += b4.z; r.w += b4.w;
            }
            if (relu) {
                r.x = fmaxf(r.x, 0.f); r.y = fmaxf(r.y, 0.f);
                r.z = fmaxf(r.z, 0.f); r.w = fmaxf(r.w, 0.f);
            }
            if (resid) {
                float4 r4 = *(const float4*)(resid + (long long)mm * ldres + nn);
                r.x += r4.x; r.y += r4.y; r.z += r4.z; r.w += r4.w;
            }
            *(float4*)(C + (long long)mm * ldc + nn) = r;
        }
    }
}

// ---------------------------------------------------------------------------
// Flash attention (fp32, DK=128). Q,K,V,O are [B*T, H] with head slice h*128.
// Grid: (T/BQ, B*NH). Block: 256 threads (tx = tid&15, ty = tid>>4).
// Per thread: 4 query rows (ty*4+i), 8 output dims (tx*8+c), 2 key cols
// per tile (tx + j*16). Online softmax; P staged through smem for PV.
// ---------------------------------------------------------------------------
#define BQ 64
#define BK 32
#define SPAD 132   // padded row stride for Q/K/V tiles (floats)
#define FLASH_SMEM ((BQ*SPAD + 2*BK*SPAD + BQ*BK) * 4)

__global__ __launch_bounds__(256)
void flash_attn_kernel(const float* __restrict__ Qg, const float* __restrict__ Kg,
                       const float* __restrict__ Vg, float* __restrict__ Og,
                       int Tk, int causal)
{
    extern __shared__ float sm[];
    float* sQ = sm;                       // [BQ][SPAD]
    float* sK = sQ + BQ * SPAD;           // [BK][SPAD]
    float* sV = sK + BK * SPAD;           // [BK][SPAD]
    float* sP = sV + BK * SPAD;           // [BQ][BK]

    const int tid = threadIdx.x;
    const int tx = tid & 15, ty = tid >> 4;
    const int q0 = blockIdx.x * BQ;
    const int bh = blockIdx.y;
    const int bb = bh >> 3, hh = bh & 7;

    const float* Qp = Qg + ((long long)(bb * TT + q0)) * HH + hh * DKK;
    const float* Kp = Kg + ((long long)bb * Tk) * HH + hh * DKK;
    const float* Vp = Vg + ((long long)bb * Tk) * HH + hh * DKK;

    // load Q tile: 64x128 = 2048 float4, 8 per thread, coalesced
    #pragma unroll
    for (int i = 0; i < 8; ++i) {
        int f = i * 256 + tid;
        int row = f >> 5, c4 = (f & 31) * 4;
        *(float4*)&sQ[row * SPAD + c4] = *(const float4*)(Qp + (long long)row * HH + c4);
    }

    const float scale = 0.08838834764831845f;   // 1/sqrt(128)
    float m[4], l[4], o[4][8];
    #pragma unroll
    for (int i = 0; i < 4; ++i) {
        m[i] = -INFINITY; l[i] = 0.f;
        #pragma unroll
        for (int c = 0; c < 8; ++c) o[i][c] = 0.f;
    }

    const int nkt = causal ? (q0 / BK + 2) : (Tk / BK);

    for (int kt = 0; kt < nkt; ++kt) {
        __syncthreads();   // previous PV done before K/V overwrite
        const long long krow0 = (long long)kt * BK;
        #pragma unroll
        for (int i = 0; i < 4; ++i) {
            int f = i * 256 + tid;
            int row = f >> 5, c4 = (f & 31) * 4;
            *(float4*)&sK[row * SPAD + c4] = *(const float4*)(Kp + (krow0 + row) * HH + c4);
            *(float4*)&sV[row * SPAD + c4] = *(const float4*)(Vp + (krow0 + row) * HH + c4);
        }
        __syncthreads();

        // S = Q K^T  (rows ty*4+i, cols tx + j*16)
        float s[4][2];
        #pragma unroll
        for (int i = 0; i < 4; ++i) { s[i][0] = 0.f; s[i][1] = 0.f; }
        #pragma unroll 4
        for (int d = 0; d < DKK; d += 4) {
            float4 kv0 = *(const float4*)&sK[(tx     ) * SPAD + d];
            float4 kv1 = *(const float4*)&sK[(tx + 16) * SPAD + d];
            #pragma unroll
            for (int i = 0; i < 4; ++i) {
                float4 qv = *(const float4*)&sQ[(ty * 4 + i) * SPAD + d];
                s[i][0] += qv.x * kv0.x + qv.y * kv0.y + qv.z * kv0.z + qv.w * kv0.w;
                s[i][1] += qv.x * kv1.x + qv.y * kv1.y + qv.z * kv1.z + qv.w * kv1.w;
            }
        }

        // scale + causal mask
        #pragma unroll
        for (int i = 0; i < 4; ++i) {
            int qg = q0 + ty * 4 + i;
            #pragma unroll
            for (int j = 0; j < 2; ++j) {
                s[i][j] *= scale;
                if (causal && (kt * BK + tx + j * 16 > qg)) s[i][j] = -INFINITY;
            }
        }

        // online softmax update
        float corr[4];
        #pragma unroll
        for (int i = 0; i < 4; ++i) {
            float mx = fmaxf(s[i][0], s[i][1]);
            #pragma unroll
            for (int off = 8; off; off >>= 1)
                mx = fmaxf(mx, __shfl_xor_sync(0xffffffffu, mx, off));
            float mn = fmaxf(m[i], mx);
            corr[i] = __expf(m[i] - mn);
            float p0 = __expf(s[i][0] - mn);
            float p1 = __expf(s[i][1] - mn);
            float ts = p0 + p1;
            #pragma unroll
            for (int off = 8; off; off >>= 1)
                ts += __shfl_xor_sync(0xffffffffu, ts, off);
            l[i] = l[i] * corr[i] + ts;
            m[i] = mn;
            sP[(ty * 4 + i) * BK + tx     ] = p0;
            sP[(ty * 4 + i) * BK + tx + 16] = p1;
            #pragma unroll
            for (int c = 0; c < 8; ++c) o[i][c] *= corr[i];
        }
        __syncthreads();   // P visible

        // O += P V   (cols tx*8 .. tx*8+7)
        #pragma unroll
        for (int k4 = 0; k4 < BK; k4 += 4) {
            float4 pv[4];
            #pragma unroll
            for (int i = 0; i < 4; ++i)
                pv[i] = *(const float4*)&sP[(ty * 4 + i) * BK + k4];
            #pragma unroll
            for (int kk = 0; kk < 4; ++kk) {
                float4 v0 = *(const float4*)&sV[(k4 + kk) * SPAD + tx * 8];
                float4 v1 = *(const float4*)&sV[(k4 + kk) * SPAD + tx * 8 + 4];
                #pragma unroll
                for (int i = 0; i < 4; ++i) {
                    float p = (kk == 0) ? pv[i].x : (kk == 1) ? pv[i].y
                            : (kk == 2) ? pv[i].z : pv[i].w;
                    o[i][0] += p * v0.x; o[i][1] += p * v0.y;
                    o[i][2] += p * v0.z; o[i][3] += p * v0.w;
                    o[i][4] += p * v1.x; o[i][5] += p * v1.y;
                    o[i][6] += p * v1.z; o[i][7] += p * v1.w;
                }
            }
        }
    }

    // finalize + store
    #pragma unroll
    for (int i = 0; i < 4; ++i) {
        float inv = 1.f / l[i];
        float4 r0, r1;
        r0.x = o[i][0] * inv; r0.y = o[i][1] * inv;
        r0.z = o[i][2] * inv; r0.w = o[i][3] * inv;
        r1.x = o[i][4] * inv; r1.y = o[i][5] * inv;
        r1.z = o[i][6] * inv; r1.w = o[i][7] * inv;
        float* op = Og + ((long long)(bb * TT + q0 + ty * 4 + i)) * HH + hh * DKK + tx * 8;
        *(float4*)op = r0;
        *(float4*)(op + 4) = r1;
    }
}

// ---------------------------------------------------------------------------
// LayerNorm over last dim (1024). One block (256 threads) per row. Two-pass.
// ---------------------------------------------------------------------------
__global__ __launch_bounds__(256)
void layernorm_kernel(const float* __restrict__ x, const float* __restrict__ g,
                      const float* __restrict__ b, float* __restrict__ y)
{
    const long long row = blockIdx.x;
    const int tid = threadIdx.x;
    float4 v = ((const float4*)(x + row * HH))[tid];

    __shared__ float red[8];
    float s = v.x + v.y + v.z + v.w;
    #pragma unroll
    for (int o = 16; o; o >>= 1) s += __shfl_xor_sync(0xffffffffu, s, o);
    if ((tid & 31) == 0) red[tid >> 5] = s;
    __syncthreads();
    float mean = (red[0] + red[1] + red[2] + red[3] +
                  red[4] + red[5] + red[6] + red[7]) * (1.f / HH);
    __syncthreads();

    float dx = v.x - mean, dy = v.y - mean, dz = v.z - mean, dw = v.w - mean;
    float sq = dx * dx + dy * dy + dz * dz + dw * dw;
    #pragma unroll
    for (int o = 16; o; o >>= 1) sq += __shfl_xor_sync(0xffffffffu, sq, o);
    if ((tid & 31) == 0) red[tid >> 5] = sq;
    __syncthreads();
    float var = (red[0] + red[1] + red[2] + red[3] +
                 red[4] + red[5] + red[6] + red[7]) * (1.f / HH);
    float rstd = rsqrtf(var + 1e-5f);

    float4 g4 = ((const float4*)g)[tid];
    float4 b4 = ((const float4*)b)[tid];
    float4 o4;
    o4.x = dx * rstd * g4.x + b4.x;
    o4.y = dy * rstd * g4.y + b4.y;
    o4.z = dz * rstd * g4.z + b4.z;
    o4.w = dw * rstd * g4.w + b4.w;
    ((float4*)(y + row * HH))[tid] = o4;
}

// ---------------------------------------------------------------------------
// Host orchestration
// ---------------------------------------------------------------------------
extern "C" void kernel_launch(void* const* d_in, const int* in_sizes, int n_in,
                              void* d_out, int out_size)
{
    const float* input_ = (const float*)d_in[0];
    const float* enc    = (const float*)d_in[1];
    // d_in[2]/d_in[3]: self mask (causal triu, k=1) / cross mask (all false).
    const float* Wq_s = (const float*)d_in[4];
    const float* Wk_s = (const float*)d_in[5];
    const float* Wv_s = (const float*)d_in[6];
    const float* Wo_s = (const float*)d_in[7];
    const float* Wq_c = (const float*)d_in[8];
    const float* Wk_c = (const float*)d_in[9];
    const float* Wv_c = (const float*)d_in[10];
    const float* Wo_c = (const float*)d_in[11];
    const float* w1   = (const float*)d_in[12];
    const float* b1   = (const float*)d_in[13];
    const float* w2   = (const float*)d_in[14];
    const float* b2   = (const float*)d_in[15];
    const float* g_mmha = (const float*)d_in[16];
    const float* b_mmha = (const float*)d_in[17];
    const float* g_mha  = (const float*)d_in[18];
    const float* b_mha  = (const float*)d_in[19];
    const float* g_ffn  = (const float*)d_in[20];
    const float* b_ffn  = (const float*)d_in[21];
    float* out = (float*)d_out;

    float *xn, *q, *k, *v, *x, *z, *ctx, *hbuf;
    cudaGetSymbolAddress((void**)&xn,   ws_xn);
    cudaGetSymbolAddress((void**)&q,    ws_q);
    cudaGetSymbolAddress((void**)&k,    ws_k);
    cudaGetSymbolAddress((void**)&v,    ws_v);
    cudaGetSymbolAddress((void**)&x,    ws_x);
    cudaGetSymbolAddress((void**)&z,    ws_z);
    cudaGetSymbolAddress((void**)&ctx,  ws_ctx);
    cudaGetSymbolAddress((void**)&hbuf, ws_h);

    cudaFuncSetAttribute(flash_attn_kernel,
                         cudaFuncAttributeMaxDynamicSharedMemorySize, FLASH_SMEM);

    // plain NT projection GEMM:  C = A @ W^T (+bias/relu/resid)
    auto proj = [&](const float* A, const float* W, float* C, int M, int N, int K,
                    const float* bias, const float* resid, int relu) {
        dim3 grid(N / 128, M / 128, 1);
        gemm_tile_kernel<true><<<grid, 256>>>(A, K, W, K, C, N,
                                              M, N, K, 1.0f, bias, resid, N, relu);
    };
    auto flash = [&](const float* Q, const float* K, const float* V, float* O,
                     int Tk, int causal) {
        dim3 grid(TT / BQ, BB * NHH);
        flash_attn_kernel<<<grid, 256, FLASH_SMEM>>>(Q, K, V, O, Tk, causal);
    };

    // ---- self attention ----
    layernorm_kernel<<<MM, 256>>>(input_, g_mmha, b_mmha, xn);
    proj(xn, Wq_s, q, MM, HH, HH, nullptr, nullptr, 0);
    proj(xn, Wk_s, k, MM, HH, HH, nullptr, nullptr, 0);
    proj(xn, Wv_s, v, MM, HH, HH, nullptr, nullptr, 0);
    flash(q, k, v, ctx, TT, /*causal=*/1);
    proj(ctx, Wo_s, x, MM, HH, HH, nullptr, input_, 0);   // x = input + SA

    // ---- cross attention ----
    layernorm_kernel<<<MM, 256>>>(x, g_mha, b_mha, xn);
    proj(xn,  Wq_c, q, MM, HH, HH, nullptr, nullptr, 0);
    proj(enc, Wk_c, k, BB * TEE, HH, HH, nullptr, nullptr, 0);
    proj(enc, Wv_c, v, BB * TEE, HH, HH, nullptr, nullptr, 0);
    flash(q, k, v, ctx, TEE, /*causal=*/0);
    proj(ctx, Wo_c, z, MM, HH, HH, nullptr, x, 0);        // z = x + CA

    // ---- FFN ----
    layernorm_kernel<<<MM, 256>>>(z, g_ffn, b_ffn, xn);
    proj(xn, w1, hbuf, MM, FF, HH, b1, nullptr, 1);       // relu(xn@w1^T + b1)
    proj(hbuf, w2, out, MM, HH, FF, b2, z, 0);            // z + (h@w2^T + b2)
}

// round 5
// speedup vs baseline: 1.1075x; 1.1075x over previous
#include <cuda_runtime.h>
#include <cuda_bf16.h>
#include <math.h>
#include <stdint.h>

// Problem constants (fixed by the reference setup)
#define BB   8
#define TT   1024
#define TEE  1024
#define HH   1024
#define NHH  8
#define DKK  128
#define MM   (BB * TT)       // 8192 rows for projections
#define FF   4096            // FFN hidden

// ---------------------------------------------------------------------------
// Scratch (static device globals)
// ---------------------------------------------------------------------------
__device__ float ws_xn [MM * HH];
__device__ float ws_q  [MM * HH];
__device__ float ws_k  [MM * HH];
__device__ float ws_v  [MM * HH];
__device__ float ws_x  [MM * HH];
__device__ float ws_z  [MM * HH];
__device__ float ws_ctx[MM * HH];
__device__ float ws_h  [MM * FF];

// ---------------------------------------------------------------------------
// tf32x3 tensor-core GEMM:  C = A[M,K] @ B[N,K]^T  (+ bias/relu/resid)
// Split a = a_hi + a_lo (tf32), compute AhBh + AhBl + AlBh on tensor cores.
// CTA tile 128x128, 8 warps (2x4), warp tile 64x32, K-chunk 32,
// cp.async double-buffered smem, rows padded to 36 floats (conflict-free
// fragment loads: bank = (4*row + col) mod 32, all distinct).
// Requires: M,N % 128 == 0, K % 32 == 0, lda=ldb=K.
// ---------------------------------------------------------------------------
#define GS_LD 36
#define GEMM_SMEM (2 * 128 * GS_LD * 4 * 2)   // 2 ops * 2 bufs * 128*36 floats

__device__ __forceinline__ void split_tf32(float x, uint32_t& hi, uint32_t& lo) {
    asm("cvt.rna.tf32.f32 %0, %1;" : "=r"(hi) : "f"(x));
    float r = x - __uint_as_float(hi);
    asm("cvt.rna.tf32.f32 %0, %1;" : "=r"(lo) : "f"(r));
}

__device__ __forceinline__ void mma_tf32(float* c, const uint32_t* a, const uint32_t* b) {
    asm volatile(
        "mma.sync.aligned.m16n8k8.row.col.f32.tf32.tf32.f32 "
        "{%0,%1,%2,%3},{%4,%5,%6,%7},{%8,%9},{%0,%1,%2,%3};"
        : "+f"(c[0]), "+f"(c[1]), "+f"(c[2]), "+f"(c[3])
        : "r"(a[0]), "r"(a[1]), "r"(a[2]), "r"(a[3]), "r"(b[0]), "r"(b[1]));
}

__device__ __forceinline__ void cp_async16(uint32_t smem_addr, const void* gptr) {
    asm volatile("cp.async.cg.shared.global [%0], [%1], 16;"
                 :: "r"(smem_addr), "l"(gptr));
}

__global__ __launch_bounds__(256, 2)
void gemm_tf32_kernel(const float* __restrict__ A, int lda,
                      const float* __restrict__ B, int ldb,
                      float*       __restrict__ C, int ldc,
                      int M, int N, int K,
                      const float* __restrict__ bias,
                      const float* __restrict__ resid, int ldres,
                      int relu)
{
    extern __shared__ float sm[];
    float* As = sm;                        // [2][128][GS_LD]
    float* Bs = sm + 2 * 128 * GS_LD;      // [2][128][GS_LD]

    const int tid  = threadIdx.x;
    const int warp = tid >> 5;
    const int lane = tid & 31;
    const int wm = warp >> 2;              // 0..1
    const int wn = warp & 3;               // 0..3
    const int qr = lane >> 2;              // 0..7
    const int qc = lane & 3;               // 0..3
    const int m0 = blockIdx.y * 128;
    const int n0 = blockIdx.x * 128;

    const uint32_t sAu = (uint32_t)__cvta_generic_to_shared(As);
    const uint32_t sBu = (uint32_t)__cvta_generic_to_shared(Bs);

    float acc[4][4][4];
    #pragma unroll
    for (int mt = 0; mt < 4; ++mt)
        #pragma unroll
        for (int nt = 0; nt < 4; ++nt)
            #pragma unroll
            for (int r = 0; r < 4; ++r) acc[mt][nt][r] = 0.f;

    const int lrow = tid >> 3;             // 0..31
    const int lc4  = (tid & 7) * 4;        // 0,4,..,28

    auto issue = [&](int buf, int kk0) {
        #pragma unroll
        for (int i = 0; i < 4; ++i) {
            const int row = i * 32 + lrow;
            const uint32_t soff = (uint32_t)((buf * 128 + row) * GS_LD + lc4) * 4u;
            cp_async16(sAu + soff, A + (long long)(m0 + row) * lda + kk0 + lc4);
            cp_async16(sBu + soff, B + (long long)(n0 + row) * ldb + kk0 + lc4);
        }
        asm volatile("cp.async.commit_group;");
    };

    const int nchunks = K >> 5;            // K / 32

    issue(0, 0);
    asm volatile("cp.async.wait_group 0;");
    __syncthreads();

    for (int t = 0; t < nchunks; ++t) {
        const int buf = t & 1;
        if (t + 1 < nchunks) issue(buf ^ 1, (t + 1) * 32);

        const float* Ab = As + buf * 128 * GS_LD;
        const float* Bb = Bs + buf * 128 * GS_LD;

        #pragma unroll
        for (int k8 = 0; k8 < 4; ++k8) {
            const int k0 = k8 * 8;
            // B fragments for all 4 n-tiles (hi/lo)
            uint32_t bh[4][2], bl[4][2];
            #pragma unroll
            for (int nt = 0; nt < 4; ++nt) {
                const float* bp = Bb + (wn * 32 + nt * 8 + qr) * GS_LD + k0 + qc;
                split_tf32(bp[0], bh[nt][0], bl[nt][0]);
                split_tf32(bp[4], bh[nt][1], bl[nt][1]);
            }
            #pragma unroll
            for (int mt = 0; mt < 4; ++mt) {
                const float* ap = Ab + (wm * 64 + mt * 16 + qr) * GS_LD + k0 + qc;
                uint32_t ah[4], al[4];
                split_tf32(ap[0],             ah[0], al[0]);
                split_tf32(ap[8 * GS_LD],     ah[1], al[1]);
                split_tf32(ap[4],             ah[2], al[2]);
                split_tf32(ap[8 * GS_LD + 4], ah[3], al[3]);
                #pragma unroll
                for (int nt = 0; nt < 4; ++nt) {
                    mma_tf32(acc[mt][nt], ah, bh[nt]);   // Ah*Bh
                    mma_tf32(acc[mt][nt], ah, bl[nt]);   // Ah*Bl
                    mma_tf32(acc[mt][nt], al, bh[nt]);   // Al*Bh
                }
            }
        }

        if (t + 1 < nchunks) {
            asm volatile("cp.async.wait_group 0;");
            __syncthreads();
        }
    }

    // Epilogue: each (mt,nt) frag -> rows qr,+8 ; cols 2*qc, +1. float2 stores.
    #pragma unroll
    for (int mt = 0; mt < 4; ++mt) {
        const int row0 = m0 + wm * 64 + mt * 16 + qr;
        #pragma unroll
        for (int nt = 0; nt < 4; ++nt) {
            const int col = n0 + wn * 32 + nt * 8 + qc * 2;
            float2 v0 = make_float2(acc[mt][nt][0], acc[mt][nt][1]);  // row0
            float2 v1 = make_float2(acc[mt][nt][2], acc[mt][nt][3]);  // row0+8
            if (bias) {
                float2 b2 = *(const float2*)(bias + col);
                v0.x += b2.x; v0.y += b2.y;
                v1.x += b2.x; v1.y += b2.y;
            }
            if (relu) {
                v0.x = fmaxf(v0.x, 0.f); v0.y = fmaxf(v0.y, 0.f);
                v1.x = fmaxf(v1.x, 0.f); v1.y = fmaxf(v1.y, 0.f);
            }
            if (resid) {
                float2 r0 = *(const float2*)(resid + (long long)row0 * ldres + col);
                float2 r1 = *(const float2*)(resid + (long long)(row0 + 8) * ldres + col);
                v0.x += r0.x; v0.y += r0.y;
                v1.x += r1.x; v1.y += r1.y;
            }
            *(float2*)(C + (long long)row0 * ldc + col)       = v0;
            *(float2*)(C + (long long)(row0 + 8) * ldc + col) = v1;
        }
    }
}

// ---------------------------------------------------------------------------
// Flash attention (fp32, DK=128) — unchanged from passing R4 kernel.
// ---------------------------------------------------------------------------
#define BQ 64
#define BK 32
#define SPAD 132
#define FLASH_SMEM ((BQ*SPAD + 2*BK*SPAD + BQ*BK) * 4)

__global__ __launch_bounds__(256)
void flash_attn_kernel(const float* __restrict__ Qg, const float* __restrict__ Kg,
                       const float* __restrict__ Vg, float* __restrict__ Og,
                       int Tk, int causal)
{
    extern __shared__ float sm[];
    float* sQ = sm;
    float* sK = sQ + BQ * SPAD;
    float* sV = sK + BK * SPAD;
    float* sP = sV + BK * SPAD;

    const int tid = threadIdx.x;
    const int tx = tid & 15, ty = tid >> 4;
    const int q0 = blockIdx.x * BQ;
    const int bh = blockIdx.y;
    const int bb = bh >> 3, hh = bh & 7;

    const float* Qp = Qg + ((long long)(bb * TT + q0)) * HH + hh * DKK;
    const float* Kp = Kg + ((long long)bb * Tk) * HH + hh * DKK;
    const float* Vp = Vg + ((long long)bb * Tk) * HH + hh * DKK;

    #pragma unroll
    for (int i = 0; i < 8; ++i) {
        int f = i * 256 + tid;
        int row = f >> 5, c4 = (f & 31) * 4;
        *(float4*)&sQ[row * SPAD + c4] = *(const float4*)(Qp + (long long)row * HH + c4);
    }

    const float scale = 0.08838834764831845f;
    float m[4], l[4], o[4][8];
    #pragma unroll
    for (int i = 0; i < 4; ++i) {
        m[i] = -INFINITY; l[i] = 0.f;
        #pragma unroll
        for (int c = 0; c < 8; ++c) o[i][c] = 0.f;
    }

    const int nkt = causal ? (q0 / BK + 2) : (Tk / BK);

    for (int kt = 0; kt < nkt; ++kt) {
        __syncthreads();
        const long long krow0 = (long long)kt * BK;
        #pragma unroll
        for (int i = 0; i < 4; ++i) {
            int f = i * 256 + tid;
            int row = f >> 5, c4 = (f & 31) * 4;
            *(float4*)&sK[row * SPAD + c4] = *(const float4*)(Kp + (krow0 + row) * HH + c4);
            *(float4*)&sV[row * SPAD + c4] = *(const float4*)(Vp + (krow0 + row) * HH + c4);
        }
        __syncthreads();

        float s[4][2];
        #pragma unroll
        for (int i = 0; i < 4; ++i) { s[i][0] = 0.f; s[i][1] = 0.f; }
        #pragma unroll 4
        for (int d = 0; d < DKK; d += 4) {
            float4 kv0 = *(const float4*)&sK[(tx     ) * SPAD + d];
            float4 kv1 = *(const float4*)&sK[(tx + 16) * SPAD + d];
            #pragma unroll
            for (int i = 0; i < 4; ++i) {
                float4 qv = *(const float4*)&sQ[(ty * 4 + i) * SPAD + d];
                s[i][0] += qv.x * kv0.x + qv.y * kv0.y + qv.z * kv0.z + qv.w * kv0.w;
                s[i][1] += qv.x * kv1.x + qv.y * kv1.y + qv.z * kv1.z + qv.w * kv1.w;
            }
        }

        #pragma unroll
        for (int i = 0; i < 4; ++i) {
            int qg = q0 + ty * 4 + i;
            #pragma unroll
            for (int j = 0; j < 2; ++j) {
                s[i][j] *= scale;
                if (causal && (kt * BK + tx + j * 16 > qg)) s[i][j] = -INFINITY;
            }
        }

        float corr[4];
        #pragma unroll
        for (int i = 0; i < 4; ++i) {
            float mx = fmaxf(s[i][0], s[i][1]);
            #pragma unroll
            for (int off = 8; off; off >>= 1)
                mx = fmaxf(mx, __shfl_xor_sync(0xffffffffu, mx, off));
            float mn = fmaxf(m[i], mx);
            corr[i] = __expf(m[i] - mn);
            float p0 = __expf(s[i][0] - mn);
            float p1 = __expf(s[i][1] - mn);
            float ts = p0 + p1;
            #pragma unroll
            for (int off = 8; off; off >>= 1)
                ts += __shfl_xor_sync(0xffffffffu, ts, off);
            l[i] = l[i] * corr[i] + ts;
            m[i] = mn;
            sP[(ty * 4 + i) * BK + tx     ] = p0;
            sP[(ty * 4 + i) * BK + tx + 16] = p1;
            #pragma unroll
            for (int c = 0; c < 8; ++c) o[i][c] *= corr[i];
        }
        __syncthreads();

        #pragma unroll
        for (int k4 = 0; k4 < BK; k4 += 4) {
            float4 pv[4];
            #pragma unroll
            for (int i = 0; i < 4; ++i)
                pv[i] = *(const float4*)&sP[(ty * 4 + i) * BK + k4];
            #pragma unroll
            for (int kk = 0; kk < 4; ++kk) {
                float4 v0 = *(const float4*)&sV[(k4 + kk) * SPAD + tx * 8];
                float4 v1 = *(const float4*)&sV[(k4 + kk) * SPAD + tx * 8 + 4];
                #pragma unroll
                for (int i = 0; i < 4; ++i) {
                    float p = (kk == 0) ? pv[i].x : (kk == 1) ? pv[i].y
                            : (kk == 2) ? pv[i].z : pv[i].w;
                    o[i][0] += p * v0.x; o[i][1] += p * v0.y;
                    o[i][2] += p * v0.z; o[i][3] += p * v0.w;
                    o[i][4] += p * v1.x; o[i][5] += p * v1.y;
                    o[i][6] += p * v1.z; o[i][7] += p * v1.w;
                }
            }
        }
    }

    #pragma unroll
    for (int i = 0; i < 4; ++i) {
        float inv = 1.f / l[i];
        float4 r0, r1;
        r0.x = o[i][0] * inv; r0.y = o[i][1] * inv;
        r0.z = o[i][2] * inv; r0.w = o[i][3] * inv;
        r1.x = o[i][4] * inv; r1.y = o[i][5] * inv;
        r1.z = o[i][6] * inv; r1.w = o[i][7] * inv;
        float* op = Og + ((long long)(bb * TT + q0 + ty * 4 + i)) * HH + hh * DKK + tx * 8;
        *(float4*)op = r0;
        *(float4*)(op + 4) = r1;
    }
}

// ---------------------------------------------------------------------------
// LayerNorm over last dim (1024). One block (256 threads) per row.
// ---------------------------------------------------------------------------
__global__ __launch_bounds__(256)
void layernorm_kernel(const float* __restrict__ x, const float* __restrict__ g,
                      const float* __restrict__ b, float* __restrict__ y)
{
    const long long row = blockIdx.x;
    const int tid = threadIdx.x;
    float4 v = ((const float4*)(x + row * HH))[tid];

    __shared__ float red[8];
    float s = v.x + v.y + v.z + v.w;
    #pragma unroll
    for (int o = 16; o; o >>= 1) s += __shfl_xor_sync(0xffffffffu, s, o);
    if ((tid & 31) == 0) red[tid >> 5] = s;
    __syncthreads();
    float mean = (red[0] + red[1] + red[2] + red[3] +
                  red[4] + red[5] + red[6] + red[7]) * (1.f / HH);
    __syncthreads();

    float dx = v.x - mean, dy = v.y - mean, dz = v.z - mean, dw = v.w - mean;
    float sq = dx * dx + dy * dy + dz * dz + dw * dw;
    #pragma unroll
    for (int o = 16; o; o >>= 1) sq += __shfl_xor_sync(0xffffffffu, sq, o);
    if ((tid & 31) == 0) red[tid >> 5] = sq;
    __syncthreads();
    float var = (red[0] + red[1] + red[2] + red[3] +
                 red[4] + red[5] + red[6] + red[7]) * (1.f / HH);
    float rstd = rsqrtf(var + 1e-5f);

    float4 g4 = ((const float4*)g)[tid];
    float4 b4 = ((const float4*)b)[tid];
    float4 o4;
    o4.x = dx * rstd * g4.x + b4.x;
    o4.y = dy * rstd * g4.y + b4.y;
    o4.z = dz * rstd * g4.z + b4.z;
    o4.w = dw * rstd * g4.w + b4.w;
    ((float4*)(y + row * HH))[tid] = o4;
}

// ---------------------------------------------------------------------------
// Host orchestration
// ---------------------------------------------------------------------------
extern "C" void kernel_launch(void* const* d_in, const int* in_sizes, int n_in,
                              void* d_out, int out_size)
{
    const float* input_ = (const float*)d_in[0];
    const float* enc    = (const float*)d_in[1];
    const float* Wq_s = (const float*)d_in[4];
    const float* Wk_s = (const float*)d_in[5];
    const float* Wv_s = (const float*)d_in[6];
    const float* Wo_s = (const float*)d_in[7];
    const float* Wq_c = (const float*)d_in[8];
    const float* Wk_c = (const float*)d_in[9];
    const float* Wv_c = (const float*)d_in[10];
    const float* Wo_c = (const float*)d_in[11];
    const float* w1   = (const float*)d_in[12];
    const float* b1   = (const float*)d_in[13];
    const float* w2   = (const float*)d_in[14];
    const float* b2   = (const float*)d_in[15];
    const float* g_mmha = (const float*)d_in[16];
    const float* b_mmha = (const float*)d_in[17];
    const float* g_mha  = (const float*)d_in[18];
    const float* b_mha  = (const float*)d_in[19];
    const float* g_ffn  = (const float*)d_in[20];
    const float* b_ffn  = (const float*)d_in[21];
    float* out = (float*)d_out;

    float *xn, *q, *k, *v, *x, *z, *ctx, *hbuf;
    cudaGetSymbolAddress((void**)&xn,   ws_xn);
    cudaGetSymbolAddress((void**)&q,    ws_q);
    cudaGetSymbolAddress((void**)&k,    ws_k);
    cudaGetSymbolAddress((void**)&v,    ws_v);
    cudaGetSymbolAddress((void**)&x,    ws_x);
    cudaGetSymbolAddress((void**)&z,    ws_z);
    cudaGetSymbolAddress((void**)&ctx,  ws_ctx);
    cudaGetSymbolAddress((void**)&hbuf, ws_h);

    cudaFuncSetAttribute(flash_attn_kernel,
                         cudaFuncAttributeMaxDynamicSharedMemorySize, FLASH_SMEM);
    cudaFuncSetAttribute(gemm_tf32_kernel,
                         cudaFuncAttributeMaxDynamicSharedMemorySize, GEMM_SMEM);

    // C = A @ W^T (+bias/relu/resid) on tensor cores (tf32x3)
    auto proj = [&](const float* A, const float* W, float* C, int M, int N, int K,
                    const float* bias, const float* resid, int relu) {
        dim3 grid(N / 128, M / 128, 1);
        gemm_tf32_kernel<<<grid, 256, GEMM_SMEM>>>(A, K, W, K, C, N,
                                                   M, N, K, bias, resid, N, relu);
    };
    auto flash = [&](const float* Q, const float* K, const float* V, float* O,
                     int Tk, int causal) {
        dim3 grid(TT / BQ, BB * NHH);
        flash_attn_kernel<<<grid, 256, FLASH_SMEM>>>(Q, K, V, O, Tk, causal);
    };

    // ---- self attention ----
    layernorm_kernel<<<MM, 256>>>(input_, g_mmha, b_mmha, xn);
    proj(xn, Wq_s, q, MM, HH, HH, nullptr, nullptr, 0);
    proj(xn, Wk_s, k, MM, HH, HH, nullptr, nullptr, 0);
    proj(xn, Wv_s, v, MM, HH, HH, nullptr, nullptr, 0);
    flash(q, k, v, ctx, TT, /*causal=*/1);
    proj(ctx, Wo_s, x, MM, HH, HH, nullptr, input_, 0);

    // ---- cross attention ----
    layernorm_kernel<<<MM, 256>>>(x, g_mha, b_mha, xn);
    proj(xn,  Wq_c, q, MM, HH, HH, nullptr, nullptr, 0);
    proj(enc, Wk_c, k, BB * TEE, HH, HH, nullptr, nullptr, 0);
    proj(enc, Wv_c, v, BB * TEE, HH, HH, nullptr, nullptr, 0);
    flash(q, k, v, ctx, TEE, /*causal=*/0);
    proj(ctx, Wo_c, z, MM, HH, HH, nullptr, x, 0);

    // ---- FFN ----
    layernorm_kernel<<<MM, 256>>>(z, g_ffn, b_ffn, xn);
    proj(xn, w1, hbuf, MM, FF, HH, b1, nullptr, 1);
    proj(hbuf, w2, out, MM, HH, FF, b2, z, 0);
}